// round 1
// baseline (speedup 1.0000x reference)
#include <cuda_runtime.h>

#define NN   100000
#define EEMAX 3200000
#define F1   16
#define F2   40
#define DIN  512

// Scratch (static device globals — no allocation allowed)
__device__ float g_deg [NN];
__device__ float g_dinv[NN];
__device__ float g_xw  [NN * F1];
__device__ float g_h   [NN * F1];
__device__ float g_hd  [NN * F1];
__device__ float g_g   [NN * F1];

// ---------------------------------------------------------------------------
// deg init: self-loop contributes exactly 1 to every node
__global__ void k_init_deg() {
    int v = blockIdx.x * blockDim.x + threadIdx.x;
    if (v < NN) g_deg[v] = 1.0f;
}

// deg accumulation over random edges (count of col occurrences)
__global__ void k_deg(const int* __restrict__ col, int E) {
    int e = blockIdx.x * blockDim.x + threadIdx.x;
    if (e < E) atomicAdd(&g_deg[col[e]], 1.0f);
}

// ---------------------------------------------------------------------------
// xw = x @ W1 ; dinv = rsqrt(deg) ; h initialized with self-loop term
__global__ __launch_bounds__(256) void k_gemm1(const float* __restrict__ x,
                                               const float* __restrict__ W1) {
    __shared__ float4 sW[DIN * 4];            // W1[512][16] as float4[512][4]
    const float4* Wv = (const float4*)W1;
    for (int i = threadIdx.x; i < DIN * 4; i += 256) sW[i] = Wv[i];
    __syncthreads();

    int v = blockIdx.x * 256 + threadIdx.x;
    if (v >= NN) return;

    float acc[16];
#pragma unroll
    for (int i = 0; i < 16; ++i) acc[i] = 0.0f;

    const float4* xr = (const float4*)(x + (size_t)v * DIN);
#pragma unroll 4
    for (int j = 0; j < DIN / 4; ++j) {
        float4 xv = xr[j];
#pragma unroll
        for (int u = 0; u < 4; ++u) {
            float xs = (u == 0) ? xv.x : (u == 1) ? xv.y : (u == 2) ? xv.z : xv.w;
            int k = j * 4 + u;
#pragma unroll
            for (int q = 0; q < 4; ++q) {
                float4 w = sW[k * 4 + q];
                acc[q * 4 + 0] += xs * w.x;
                acc[q * 4 + 1] += xs * w.y;
                acc[q * 4 + 2] += xs * w.z;
                acc[q * 4 + 3] += xs * w.w;
            }
        }
    }

    float d = rsqrtf(g_deg[v]);
    g_dinv[v] = d;
    float s = d * d;                           // self-loop norm = dinv^2
    float4* xwv = (float4*)(g_xw + (size_t)v * F1);
    float4* hv  = (float4*)(g_h  + (size_t)v * F1);
#pragma unroll
    for (int q = 0; q < 4; ++q) {
        float4 a = make_float4(acc[q*4], acc[q*4+1], acc[q*4+2], acc[q*4+3]);
        xwv[q] = a;
        hv[q]  = make_float4(s*a.x, s*a.y, s*a.z, s*a.w);
    }
}

// ---------------------------------------------------------------------------
// Vector reduce-add to global (sm_90+): 1 RED.128 instead of 4 scalar atomics
__device__ __forceinline__ void red4(float* p, float a, float b, float c, float d) {
    asm volatile("red.global.add.v4.f32 [%0], {%1,%2,%3,%4};"
                 :: "l"(p), "f"(a), "f"(b), "f"(c), "f"(d) : "memory");
}

// Edge scatter: dst[col] += dinv[row]*dinv[col] * src[row]   (16 feats)
// layer 0: src=g_xw dst=g_h ; layer 1: src=g_hd dst=g_g
__global__ void k_scatter(const int* __restrict__ row, const int* __restrict__ col,
                          int E, int layer) {
    int e = blockIdx.x * blockDim.x + threadIdx.x;
    if (e >= E) return;
    int r = row[e], c = col[e];
    float nrm = g_dinv[r] * g_dinv[c];
    const float* src = (layer == 0) ? g_xw : g_hd;
    float*       dst = (layer == 0) ? g_h  : g_g;
    const float4* s = (const float4*)(src + (size_t)r * F1);
    float*        d = dst + (size_t)c * F1;
#pragma unroll
    for (int q = 0; q < 4; ++q) {
        float4 a = s[q];
        red4(d + q * 4, nrm * a.x, nrm * a.y, nrm * a.z, nrm * a.w);
    }
}

// ---------------------------------------------------------------------------
// JAX threefry2x32 (partitionable counter scheme): key=(0,42), ctr=(0, idx).
// bernoulli(0.5) keep  <=>  MSB(out0 ^ out1) == 0
__device__ __forceinline__ unsigned tf_keep_bits(unsigned idx) {
    const unsigned k0 = 0u, k1 = 42u, k2 = 0u ^ 42u ^ 0x1BD11BDAu;
    unsigned x0 = k0;            // counter hi word (0) + ks0
    unsigned x1 = idx + k1;      // counter lo word + ks1
#define TFR(r) { x0 += x1; x1 = (x1 << (r)) | (x1 >> (32 - (r))); x1 ^= x0; }
    TFR(13) TFR(15) TFR(26) TFR(6)   x0 += k1; x1 += k2 + 1u;
    TFR(17) TFR(29) TFR(16) TFR(24)  x0 += k2; x1 += k0 + 2u;
    TFR(13) TFR(15) TFR(26) TFR(6)   x0 += k0; x1 += k1 + 3u;
    TFR(17) TFR(29) TFR(16) TFR(24)  x0 += k1; x1 += k2 + 4u;
    TFR(13) TFR(15) TFR(26) TFR(6)   x0 += k2; x1 += k0 + 5u;
#undef TFR
    return x0 ^ x1;
}

// dropout (training, p=0.5) on (h + b1); also init g with self-loop term
__global__ void k_dropout(const float* __restrict__ b1) {
    int idx = blockIdx.x * blockDim.x + threadIdx.x;
    if (idx >= NN * F1) return;
    int v = idx >> 4, f = idx & 15;
    unsigned bits = tf_keep_bits((unsigned)idx);
    float val = 0.0f;
    if (!(bits & 0x80000000u)) val = 2.0f * (g_h[idx] + b1[f]);
    g_hd[idx] = val;
    float d = g_dinv[v];
    g_g[idx] = d * d * val;
}

// ---------------------------------------------------------------------------
// out = g @ W2 + b2     [100000,16] @ [16,40]
__global__ __launch_bounds__(256) void k_out(const float* __restrict__ W2,
                                             const float* __restrict__ b2,
                                             float* __restrict__ out) {
    __shared__ float sW[F1 * F2];
    __shared__ float sb[F2];
    for (int i = threadIdx.x; i < F1 * F2; i += 256) sW[i] = W2[i];
    if (threadIdx.x < F2) sb[threadIdx.x] = b2[threadIdx.x];
    __syncthreads();

    int v = blockIdx.x * 256 + threadIdx.x;
    if (v >= NN) return;

    float in[16];
    const float4* gv = (const float4*)(g_g + (size_t)v * F1);
#pragma unroll
    for (int q = 0; q < 4; ++q) {
        float4 a = gv[q];
        in[q*4+0] = a.x; in[q*4+1] = a.y; in[q*4+2] = a.z; in[q*4+3] = a.w;
    }

    float acc[F2];
#pragma unroll
    for (int f = 0; f < F2; ++f) acc[f] = sb[f];
#pragma unroll
    for (int k = 0; k < F1; ++k) {
        float xs = in[k];
        const float4* wrow = (const float4*)(sW + k * F2);
#pragma unroll
        for (int q = 0; q < F2 / 4; ++q) {
            float4 w = wrow[q];
            acc[q*4+0] += xs * w.x;
            acc[q*4+1] += xs * w.y;
            acc[q*4+2] += xs * w.z;
            acc[q*4+3] += xs * w.w;
        }
    }

    float4* ov = (float4*)(out + (size_t)v * F2);   // 160B per row, 16B aligned
#pragma unroll
    for (int q = 0; q < F2 / 4; ++q)
        ov[q] = make_float4(acc[q*4], acc[q*4+1], acc[q*4+2], acc[q*4+3]);
}

// ---------------------------------------------------------------------------
extern "C" void kernel_launch(void* const* d_in, const int* in_sizes, int n_in,
                              void* d_out, int out_size) {
    const float* x  = (const float*)d_in[0];
    const int*   ei = (const int*)  d_in[1];
    const float* W1 = (const float*)d_in[2];
    const float* b1 = (const float*)d_in[3];
    const float* W2 = (const float*)d_in[4];
    const float* b2 = (const float*)d_in[5];
    float* out = (float*)d_out;

    int E = in_sizes[1] / 2;                  // 3,200,000
    if (E > EEMAX) E = EEMAX;
    const int* row = ei;
    const int* col = ei + E;

    const int TB = 256;
    int nb_n = (NN + TB - 1) / TB;
    int nb_e = (E + TB - 1) / TB;
    int nb_h = (NN * F1 + TB - 1) / TB;

    k_init_deg<<<nb_n, TB>>>();
    k_deg     <<<nb_e, TB>>>(col, E);
    k_gemm1   <<<nb_n, TB>>>(x, W1);          // xw, dinv, h(self-loop init)
    k_scatter <<<nb_e, TB>>>(row, col, E, 0); // h += norm * xw[row]
    k_dropout <<<nb_h, TB>>>(b1);             // hd, g(self-loop init)
    k_scatter <<<nb_e, TB>>>(row, col, E, 1); // g += norm * hd[row]
    k_out     <<<nb_n, TB>>>(W2, b2, out);    // out = g @ W2 + b2
}

// round 2
// speedup vs baseline: 1.5592x; 1.5592x over previous
#include <cuda_runtime.h>

#define NN    100000
#define EEMAX 3200000
#define F1    16
#define F2    40
#define DIN   512

// Scratch (static device globals — no allocation allowed)
__device__ int   g_cnt [NN];        // edge in-degree (without self-loop)
__device__ int   g_off [NN];        // CSR offsets (exclusive scan of cnt)
__device__ int   g_cur [NN];        // fill cursors
__device__ int   g_adj [EEMAX];     // CSR: source node per slot
__device__ int   g_bsum[128];       // scan block sums
__device__ float g_dinv[NN];
__device__ float g_src [NN * F1];   // xws = dinv * (x @ W1)
__device__ float g_hds [NN * F1];   // dinv * dropout(h + b1)

// ---------------------------------------------------------------------------
__global__ void k_zero() {
    int v = blockIdx.x * blockDim.x + threadIdx.x;
    if (v < NN) g_cnt[v] = 0;
}

__global__ void k_count(const int* __restrict__ col, int E) {
    int e = blockIdx.x * blockDim.x + threadIdx.x;
    if (e < E) atomicAdd(&g_cnt[col[e]], 1);
}

// ---------------------------------------------------------------------------
// Two-level exclusive scan of g_cnt -> g_off
__global__ __launch_bounds__(1024) void k_scan1() {
    __shared__ int wsum[32];
    int i = blockIdx.x * 1024 + threadIdx.x;
    int v = (i < NN) ? g_cnt[i] : 0;
    int lane = threadIdx.x & 31, wid = threadIdx.x >> 5;
    int x = v;
#pragma unroll
    for (int d = 1; d < 32; d <<= 1) {
        int y = __shfl_up_sync(0xffffffffu, x, d);
        if (lane >= d) x += y;
    }
    if (lane == 31) wsum[wid] = x;
    __syncthreads();
    if (wid == 0) {
        int w = wsum[lane];
#pragma unroll
        for (int d = 1; d < 32; d <<= 1) {
            int y = __shfl_up_sync(0xffffffffu, w, d);
            if (lane >= d) w += y;
        }
        wsum[lane] = w;
    }
    __syncthreads();
    int incl = x + (wid > 0 ? wsum[wid - 1] : 0);
    if (i < NN) g_off[i] = incl - v;               // block-local exclusive
    if (threadIdx.x == 1023) g_bsum[blockIdx.x] = incl;
}

__global__ void k_scan2(int nb) {
    if (threadIdx.x == 0 && blockIdx.x == 0) {
        int s = 0;
        for (int b = 0; b < nb; ++b) { int t = g_bsum[b]; g_bsum[b] = s; s += t; }
    }
}

__global__ void k_scan3() {
    int i = blockIdx.x * blockDim.x + threadIdx.x;
    if (i < NN) {
        int o = g_off[i] + g_bsum[i >> 10];
        g_off[i] = o;
        g_cur[i] = o;
    }
}

// ---------------------------------------------------------------------------
__global__ void k_fill(const int* __restrict__ row, const int* __restrict__ col, int E) {
    int e = blockIdx.x * blockDim.x + threadIdx.x;
    if (e >= E) return;
    int c = col[e];
    int pos = atomicAdd(&g_cur[c], 1);
    g_adj[pos] = row[e];
}

// ---------------------------------------------------------------------------
// xw = x @ W1 ; dinv = rsqrt(deg) ; g_src = dinv * xw
__global__ __launch_bounds__(256) void k_gemm1(const float* __restrict__ x,
                                               const float* __restrict__ W1) {
    __shared__ float4 sW[DIN * 4];               // W1[512][16] as float4[512][4]
    const float4* Wv = (const float4*)W1;
    for (int i = threadIdx.x; i < DIN * 4; i += 256) sW[i] = Wv[i];
    __syncthreads();

    int v = blockIdx.x * 256 + threadIdx.x;
    if (v >= NN) return;

    float acc[16];
#pragma unroll
    for (int i = 0; i < 16; ++i) acc[i] = 0.0f;

    const float4* xr = (const float4*)(x + (size_t)v * DIN);
#pragma unroll 4
    for (int j = 0; j < DIN / 4; ++j) {
        float4 xv = xr[j];
#pragma unroll
        for (int u = 0; u < 4; ++u) {
            float xs = (u == 0) ? xv.x : (u == 1) ? xv.y : (u == 2) ? xv.z : xv.w;
            int k = j * 4 + u;
#pragma unroll
            for (int q = 0; q < 4; ++q) {
                float4 w = sW[k * 4 + q];
                acc[q * 4 + 0] += xs * w.x;
                acc[q * 4 + 1] += xs * w.y;
                acc[q * 4 + 2] += xs * w.z;
                acc[q * 4 + 3] += xs * w.w;
            }
        }
    }

    float d = rsqrtf((float)(g_cnt[v] + 1));      // +1 self-loop
    g_dinv[v] = d;
    float4* sv = (float4*)(g_src + (size_t)v * F1);
#pragma unroll
    for (int q = 0; q < 4; ++q)
        sv[q] = make_float4(d * acc[q*4], d * acc[q*4+1], d * acc[q*4+2], d * acc[q*4+3]);
}

// ---------------------------------------------------------------------------
// JAX threefry2x32 (partitionable): key=(0,42), ctr=(0, idx).
// bernoulli(0.5) keep  <=>  MSB(out0 ^ out1) == 0
__device__ __forceinline__ unsigned tf_keep_bits(unsigned idx) {
    const unsigned k0 = 0u, k1 = 42u, k2 = 0u ^ 42u ^ 0x1BD11BDAu;
    unsigned x0 = k0;
    unsigned x1 = idx + k1;
#define TFR(r) { x0 += x1; x1 = (x1 << (r)) | (x1 >> (32 - (r))); x1 ^= x0; }
    TFR(13) TFR(15) TFR(26) TFR(6)   x0 += k1; x1 += k2 + 1u;
    TFR(17) TFR(29) TFR(16) TFR(24)  x0 += k2; x1 += k0 + 2u;
    TFR(13) TFR(15) TFR(26) TFR(6)   x0 += k0; x1 += k1 + 3u;
    TFR(17) TFR(29) TFR(16) TFR(24)  x0 += k1; x1 += k2 + 4u;
    TFR(13) TFR(15) TFR(26) TFR(6)   x0 += k2; x1 += k0 + 5u;
#undef TFR
    return x0 ^ x1;
}

// ---------------------------------------------------------------------------
// Layer-1 aggregation (gather over CSR) + dropout fused.
// 4 threads per node, each owns one float4 of the 16 features.
// g_hds[t] = dinv[t] * dropout( dinv[t]*acc + b1 )
__global__ __launch_bounds__(256) void k_agg1(const float* __restrict__ b1) {
    int tid = blockIdx.x * 64 + (threadIdx.x >> 2);
    int q   = threadIdx.x & 3;
    bool valid = tid < NN;
    int t = valid ? tid : NN - 1;

    const float4* src = (const float4*)g_src;
    float4 acc = src[t * 4 + q];                  // self-loop term
    int beg = g_off[t], end = beg + g_cnt[t];

    int pos = beg;
    for (; pos + 4 <= end; pos += 4) {
        int r0 = g_adj[pos], r1 = g_adj[pos+1], r2 = g_adj[pos+2], r3 = g_adj[pos+3];
        float4 s0 = src[r0*4+q], s1 = src[r1*4+q], s2 = src[r2*4+q], s3 = src[r3*4+q];
        acc.x += (s0.x + s1.x) + (s2.x + s3.x);
        acc.y += (s0.y + s1.y) + (s2.y + s3.y);
        acc.z += (s0.z + s1.z) + (s2.z + s3.z);
        acc.w += (s0.w + s1.w) + (s2.w + s3.w);
    }
    for (; pos < end; ++pos) {
        float4 s = src[g_adj[pos] * 4 + q];
        acc.x += s.x; acc.y += s.y; acc.z += s.z; acc.w += s.w;
    }
    if (!valid) return;

    float d = g_dinv[t];
    float4 bb = ((const float4*)b1)[q];
    unsigned idx = (unsigned)(t * 16 + q * 4);
    float h0 = d * acc.x + bb.x, h1 = d * acc.y + bb.y;
    float h2 = d * acc.z + bb.z, h3 = d * acc.w + bb.w;
    float o0 = (tf_keep_bits(idx + 0) & 0x80000000u) ? 0.0f : 2.0f * d * h0;
    float o1 = (tf_keep_bits(idx + 1) & 0x80000000u) ? 0.0f : 2.0f * d * h1;
    float o2 = (tf_keep_bits(idx + 2) & 0x80000000u) ? 0.0f : 2.0f * d * h2;
    float o3 = (tf_keep_bits(idx + 3) & 0x80000000u) ? 0.0f : 2.0f * d * h3;
    ((float4*)g_hds)[t * 4 + q] = make_float4(o0, o1, o2, o3);
}

// ---------------------------------------------------------------------------
// Layer-2 aggregation + (16x40 GEMM + b2) fused; out written directly.
__global__ __launch_bounds__(256) void k_agg2(const float* __restrict__ W2,
                                              const float* __restrict__ b2,
                                              float* __restrict__ out) {
    __shared__ float sW[F1 * F2];
    __shared__ float sb[F2];
    for (int i = threadIdx.x; i < F1 * F2; i += 256) sW[i] = W2[i];
    if (threadIdx.x < F2) sb[threadIdx.x] = b2[threadIdx.x];
    __syncthreads();

    int tid = blockIdx.x * 64 + (threadIdx.x >> 2);
    int q   = threadIdx.x & 3;
    bool valid = tid < NN;
    int t = valid ? tid : NN - 1;

    const float4* src = (const float4*)g_hds;
    float4 acc = src[t * 4 + q];                  // self-loop term
    int beg = g_off[t], end = beg + g_cnt[t];

    int pos = beg;
    for (; pos + 4 <= end; pos += 4) {
        int r0 = g_adj[pos], r1 = g_adj[pos+1], r2 = g_adj[pos+2], r3 = g_adj[pos+3];
        float4 s0 = src[r0*4+q], s1 = src[r1*4+q], s2 = src[r2*4+q], s3 = src[r3*4+q];
        acc.x += (s0.x + s1.x) + (s2.x + s3.x);
        acc.y += (s0.y + s1.y) + (s2.y + s3.y);
        acc.z += (s0.z + s1.z) + (s2.z + s3.z);
        acc.w += (s0.w + s1.w) + (s2.w + s3.w);
    }
    for (; pos < end; ++pos) {
        float4 s = src[g_adj[pos] * 4 + q];
        acc.x += s.x; acc.y += s.y; acc.z += s.z; acc.w += s.w;
    }

    float d = g_dinv[t];
    acc.x *= d; acc.y *= d; acc.z *= d; acc.w *= d;

    // assemble all 16 features into each lane via width-4 shuffles
    float gg[16];
#pragma unroll
    for (int s = 0; s < 4; ++s) {
        gg[s*4+0] = __shfl_sync(0xffffffffu, acc.x, s, 4);
        gg[s*4+1] = __shfl_sync(0xffffffffu, acc.y, s, 4);
        gg[s*4+2] = __shfl_sync(0xffffffffu, acc.z, s, 4);
        gg[s*4+3] = __shfl_sync(0xffffffffu, acc.w, s, 4);
    }

    // each lane computes 10 of the 40 outputs: f in [q*10, q*10+10)
    float o[10];
#pragma unroll
    for (int j = 0; j < 10; ++j) o[j] = sb[q * 10 + j];
#pragma unroll
    for (int k = 0; k < 16; ++k) {
        float gv = gg[k];
        const float* wr = sW + k * F2 + q * 10;
#pragma unroll
        for (int j = 0; j < 10; ++j) o[j] += gv * wr[j];
    }

    if (valid) {
        float* op = out + (size_t)t * F2 + q * 10;
#pragma unroll
        for (int j = 0; j < 10; ++j) op[j] = o[j];
    }
}

// ---------------------------------------------------------------------------
extern "C" void kernel_launch(void* const* d_in, const int* in_sizes, int n_in,
                              void* d_out, int out_size) {
    const float* x  = (const float*)d_in[0];
    const int*   ei = (const int*)  d_in[1];
    const float* W1 = (const float*)d_in[2];
    const float* b1 = (const float*)d_in[3];
    const float* W2 = (const float*)d_in[4];
    const float* b2 = (const float*)d_in[5];
    float* out = (float*)d_out;

    int E = in_sizes[1] / 2;                  // 3,200,000
    if (E > EEMAX) E = EEMAX;
    const int* row = ei;
    const int* col = ei + E;

    const int TB = 256;
    int nb_n = (NN + TB - 1) / TB;
    int nb_e = (E + TB - 1) / TB;
    int nb_s = (NN + 1023) / 1024;            // scan blocks (98)
    int nb_a = (NN + 63) / 64;                // agg blocks (4 thr/node)

    k_zero  <<<nb_n, TB>>>();
    k_count <<<nb_e, TB>>>(col, E);
    k_scan1 <<<nb_s, 1024>>>();
    k_scan2 <<<1, 32>>>(nb_s);
    k_scan3 <<<nb_n, TB>>>();
    k_fill  <<<nb_e, TB>>>(row, col, E);
    k_gemm1 <<<nb_n, TB>>>(x, W1);            // g_src = dinv * (x @ W1)
    k_agg1  <<<nb_a, TB>>>(b1);               // g_hds (dropout fused)
    k_agg2  <<<nb_a, TB>>>(W2, b2, out);      // out (GEMM fused)
}